// round 9
// baseline (speedup 1.0000x reference)
#include <cuda_runtime.h>
#include <math.h>

// ---------------------------------------------------------------------------
// VQ-VAE forward.  B=16, L=156, P=8, H=W=128, codebook 512x8.
// R9: issue-bound fix for tf32 convmma:
//     - NT=8 (MT=128) tiles on e1/d2 (A-load amortization)
//     - slab-row hoisted A fragments + ROWS output rows per block
//     - e3 ROWS=4 (staging reuse), d3 single MT=80 launch
// ---------------------------------------------------------------------------

#define BATCH 16
#define HW    16384   // 128*128

__device__ __forceinline__ float to_tf32(float x) {
    unsigned u; asm("cvt.rna.tf32.f32 %0, %1;" : "=r"(u) : "f"(x));
    return __uint_as_float(u);
}
__device__ __forceinline__ void mma_tf32(float c[4], const float a[4], float2 b) {
    asm volatile("mma.sync.aligned.m16n8k8.row.col.f32.tf32.tf32.f32 "
        "{%0,%1,%2,%3}, {%4,%5,%6,%7}, {%8,%9}, {%0,%1,%2,%3};"
        : "+f"(c[0]), "+f"(c[1]), "+f"(c[2]), "+f"(c[3])
        : "r"(__float_as_uint(a[0])), "r"(__float_as_uint(a[1])),
          "r"(__float_as_uint(a[2])), "r"(__float_as_uint(a[3])),
          "r"(__float_as_uint(b.x)), "r"(__float_as_uint(b.y)));
}

// Static device scratch (allocation-free rule).
__device__ float g_z1[BATCH * 128 * HW];
__device__ float g_z2[BATCH *  64 * HW];
__device__ float g_z3[BATCH *   8 * HW];
__device__ float g_q [BATCH *   8 * HW];
__device__ float g_y1[BATCH *  64 * HW];
__device__ float g_y2[BATCH * 128 * HW];
// tf32 mma weights: [chunk][tap 9][CO_PAD][8 ci-perm], perm p -> ci = (p>>1)+4*(p&1)
__device__ float g_mw_e1[20 * 9 * 128 * 8];
__device__ float g_mw_e2[16 * 9 *  64 * 8];
__device__ float g_mw_e3[ 8 * 9 *  16 * 8];
__device__ float g_mw_d1[ 1 * 9 *  64 * 8];
__device__ float g_mw_d2[ 8 * 9 * 128 * 8];
__device__ float g_mw_d3[16 * 9 * 160 * 8];
__device__ double g_part[256];

// ---------------------------------------------------------------------------
// Weight packing into mma layout.  transposed=0: Conv2d OIHW.
// transposed=1: ConvTranspose (in,out,kh,kw) -> IO swap + spatial flip.
// ---------------------------------------------------------------------------
__device__ void pack_mma(const float* __restrict__ w, float* __restrict__ out,
                         int CIN, int COUT, int CO_PAD, int transposed, int idx) {
    int p     = idx & 7;
    int co    = (idx >> 3) % CO_PAD;
    int tap   = ((idx >> 3) / CO_PAD) % 9;
    int chunk = ((idx >> 3) / CO_PAD) / 9;
    int ci    = chunk * 8 + (p >> 1) + 4 * (p & 1);
    float v = 0.f;
    if (co < COUT && ci < CIN)
        v = transposed ? w[((size_t)ci * COUT + co) * 9 + (8 - tap)]
                       : w[((size_t)co * CIN + ci) * 9 + tap];
    out[idx] = to_tf32(v);
}

__global__ void pack_all(const float* e1w, const float* e2w, const float* e3w,
                         const float* d1w, const float* d2w, const float* d3w,
                         float* me1, float* me2, float* me3,
                         float* md1, float* md2, float* md3) {
    int idx = blockIdx.x * 256 + threadIdx.x;
    if (idx < 184320) { pack_mma(e1w, me1, 156, 128, 128, 0, idx); return; }
    idx -= 184320;
    if (idx < 73728)  { pack_mma(e2w, me2, 128,  64,  64, 0, idx); return; }
    idx -= 73728;
    if (idx < 9216)   { pack_mma(e3w, me3,  64,   8,  16, 0, idx); return; }
    idx -= 9216;
    if (idx < 4608)   { pack_mma(d1w, md1,   8,  64,  64, 1, idx); return; }
    idx -= 4608;
    if (idx < 73728)  { pack_mma(d2w, md2,  64, 128, 128, 1, idx); return; }
    idx -= 73728;
    if (idx < 184320) { pack_mma(d3w, md3, 128, 156, 160, 1, idx); }
}

__device__ __forceinline__ float apply_act(float v, int ACT) {
    if (ACT == 1) return fmaxf(v, 0.f);
    if (ACT == 2) return 1.f / (1.f + __expf(-v));
    return v;
}

// ---------------------------------------------------------------------------
// tf32 tensor-core 3x3 same-conv.  Block = (n, ROWS output rows, MT co).
// 8 warps: wm = warp&3 -> 32-px span, wn = warp>>2 -> MT/2 co span.
// Mainloop iterates SLAB = ROWS+2 input rows; A fragments for a slab row are
// hoisted once into v[2][2][6] and consumed by every (output row r, dh=sr-r)
// pair and every dw via register select -> no per-tap A reloads.
// ---------------------------------------------------------------------------
template<int ROWS, int CIN, int COUT, int MT, int ACT, int CO_OFF, int CO_PAD, int NBLK>
__global__ __launch_bounds__(256, NBLK)
void convmma(const float* __restrict__ in, const float* __restrict__ mw,
             const float* __restrict__ bias, float* __restrict__ out) {
    constexpr int CHUNKS = (CIN + 7) / 8;
    constexpr int SLAB   = ROWS + 2;
    constexpr int ROWSTR = 136;
    constexpr int NT     = MT / 16;   // n-tiles per warp

    extern __shared__ float smem[];
    float* s_in = smem;                      // [8 ci][SLAB rows][ROWSTR]
    float* s_w  = smem + 8 * SLAB * ROWSTR;  // [9 tap][MT co][8 perm]

    const int n    = blockIdx.z;
    const int h0   = blockIdx.x * ROWS;
    const int cob0 = CO_OFF + blockIdx.y * MT;
    const int tid  = threadIdx.x;
    const int lane = tid & 31;
    const int warp = tid >> 5;
    const int wm   = warp & 3;
    const int wn   = warp >> 2;
    const int r4   = lane & 3;    // t%4  (k index)
    const int r4h  = lane >> 2;   // t/4  (m/n index)
    const int pxb  = wm * 32;
    const int col  = wn * (MT / 2);

    const float* inN = in + (size_t)n * CIN * HW;

    // zero halo columns once
    if (tid < 8 * SLAB) {
        float* row = s_in + tid * ROWSTR;
        row[0] = 0.f; row[1] = 0.f; row[2] = 0.f; row[3] = 0.f;
        row[132] = 0.f; row[133] = 0.f; row[134] = 0.f; row[135] = 0.f;
    }

    float C[ROWS][2][NT][4];
#pragma unroll
    for (int r = 0; r < ROWS; r++)
#pragma unroll
        for (int mt = 0; mt < 2; mt++)
#pragma unroll
            for (int nt = 0; nt < NT; nt++)
#pragma unroll
                for (int k = 0; k < 4; k++) C[r][mt][nt][k] = 0.f;

    for (int chunk = 0; chunk < CHUNKS; chunk++) {
        // ---- stage input slab (tf32-rounded)
        for (int s4 = tid; s4 < 8 * SLAB * 32; s4 += 256) {
            int kc = s4 / (SLAB * 32);
            int r  = (s4 / 32) % SLAB;
            int s  = s4 & 31;
            int ci = chunk * 8 + kc;
            int gh = h0 - 1 + r;
            float4 v = make_float4(0.f, 0.f, 0.f, 0.f);
            if (ci < CIN && gh >= 0 && gh < 128)
                v = *(const float4*)(inN + (size_t)ci * HW + gh * 128 + s * 4);
            v.x = to_tf32(v.x); v.y = to_tf32(v.y);
            v.z = to_tf32(v.z); v.w = to_tf32(v.w);
            *(float4*)(s_in + (kc * SLAB + r) * ROWSTR + 4 + s * 4) = v;
        }
        // ---- stage weights: [tap][MT co][8 perm] slice, contiguous per tap
        for (int s = tid; s < 9 * MT * 2; s += 256) {
            int tap = s / (MT * 2);
            int r   = s % (MT * 2);
            const float4* src = (const float4*)(mw +
                (((size_t)chunk * 9 + tap) * CO_PAD + cob0) * 8) + r;
            ((float4*)s_w)[tap * MT * 2 + r] = *src;
        }
        __syncthreads();

#pragma unroll
        for (int sr = 0; sr < SLAB; sr++) {
            // hoist unique A pixel values for this slab row
            float v[2][2][6];   // [mt][ci-half][pos 0,1,2,8,9,10]
#pragma unroll
            for (int mt = 0; mt < 2; mt++)
#pragma unroll
                for (int ch = 0; ch < 2; ch++) {
                    const float* bp = s_in + ((r4 + 4 * ch) * SLAB + sr) * ROWSTR
                                    + pxb + 3 + r4h + mt * 16;
                    v[mt][ch][0] = bp[0];  v[mt][ch][1] = bp[1];  v[mt][ch][2] = bp[2];
                    v[mt][ch][3] = bp[8];  v[mt][ch][4] = bp[9];  v[mt][ch][5] = bp[10];
                }
#pragma unroll
            for (int dw = 0; dw < 3; dw++) {
                float a[2][4];
#pragma unroll
                for (int mt = 0; mt < 2; mt++) {
                    a[mt][0] = v[mt][0][dw];
                    a[mt][1] = v[mt][0][3 + dw];
                    a[mt][2] = v[mt][1][dw];
                    a[mt][3] = v[mt][1][3 + dw];
                }
                constexpr int RLO_ = 0;  // silence unused in expansion
                (void)RLO_;
#pragma unroll
                for (int r = (sr - 2 < 0 ? 0 : sr - 2);
                         r <= (sr < ROWS - 1 ? sr : ROWS - 1); r++) {
                    const int tap = (sr - r) * 3 + dw;
#pragma unroll
                    for (int nt = 0; nt < NT; nt++) {
                        int co_l = col + nt * 8 + r4h;
                        float2 b = *(const float2*)(s_w + ((size_t)tap * MT + co_l) * 8 + r4 * 2);
#pragma unroll
                        for (int mt = 0; mt < 2; mt++)
                            mma_tf32(C[r][mt][nt], a[mt], b);
                    }
                }
            }
        }
        __syncthreads();
    }

    // ---- epilogue: c0 (px, co) c1 (px, co+1) c2 (px+8, co) c3 (px+8, co+1)
#pragma unroll
    for (int r = 0; r < ROWS; r++) {
#pragma unroll
        for (int mt = 0; mt < 2; mt++) {
#pragma unroll
            for (int nt = 0; nt < NT; nt++) {
                int px = pxb + mt * 16 + r4h;
                int co = cob0 + col + nt * 8 + r4 * 2;
                size_t o0 = (size_t)(h0 + r) * 128 + px;
                if (co < COUT) {
                    float b = bias[co];
                    float* op = out + ((size_t)n * COUT + co) * HW;
                    op[o0]     = apply_act(C[r][mt][nt][0] + b, ACT);
                    op[o0 + 8] = apply_act(C[r][mt][nt][2] + b, ACT);
                }
                if (co + 1 < COUT) {
                    float b = bias[co + 1];
                    float* op = out + ((size_t)n * COUT + co + 1) * HW;
                    op[o0]     = apply_act(C[r][mt][nt][1] + b, ACT);
                    op[o0 + 8] = apply_act(C[r][mt][nt][3] + b, ACT);
                }
            }
        }
    }
}

// ---------------------------------------------------------------------------
// Vector quantizer (groups of 8 along W, torch .view semantics).
// ---------------------------------------------------------------------------
__global__ __launch_bounds__(256)
void vq_kernel(const float* __restrict__ z, const float* __restrict__ emb,
               float* __restrict__ q, double* __restrict__ part) {
    __shared__ float  s_e[512 * 8];
    __shared__ float  s_hn[512];
    __shared__ double s_red[256];

    const int tid = threadIdx.x;
    for (int i = tid; i < 4096; i += 256) s_e[i] = emb[i];
    __syncthreads();
    for (int k = tid; k < 512; k += 256) {
        float s = 0.f;
#pragma unroll
        for (int j = 0; j < 8; j++) { float e = s_e[k * 8 + j]; s += e * e; }
        s_hn[k] = 0.5f * s;
    }
    __syncthreads();

    const int base = blockIdx.x * 1024 + tid;
    float v[4][8];
#pragma unroll
    for (int u = 0; u < 4; u++) {
        int vi = base + u * 256;
        float4 a = ((const float4*)z)[vi * 2];
        float4 b = ((const float4*)z)[vi * 2 + 1];
        v[u][0] = a.x; v[u][1] = a.y; v[u][2] = a.z; v[u][3] = a.w;
        v[u][4] = b.x; v[u][5] = b.y; v[u][6] = b.z; v[u][7] = b.w;
    }

    float best[4] = {3.4e38f, 3.4e38f, 3.4e38f, 3.4e38f};
    int   bk[4]   = {0, 0, 0, 0};
    for (int k = 0; k < 512; k++) {
        float e0 = s_e[k * 8 + 0], e1 = s_e[k * 8 + 1], e2 = s_e[k * 8 + 2], e3 = s_e[k * 8 + 3];
        float e4 = s_e[k * 8 + 4], e5 = s_e[k * 8 + 5], e6 = s_e[k * 8 + 6], e7 = s_e[k * 8 + 7];
        float hn = s_hn[k];
#pragma unroll
        for (int u = 0; u < 4; u++) {
            float dot = e0 * v[u][0] + e1 * v[u][1] + e2 * v[u][2] + e3 * v[u][3]
                      + e4 * v[u][4] + e5 * v[u][5] + e6 * v[u][6] + e7 * v[u][7];
            float sc = hn - dot;
            if (sc < best[u]) { best[u] = sc; bk[u] = k; }
        }
    }

    float sq = 0.f;
#pragma unroll
    for (int u = 0; u < 4; u++) {
        int vi = base + u * 256;
        int kb = bk[u];
        float4 o1, o2;
        o1.x = s_e[kb * 8 + 0]; o1.y = s_e[kb * 8 + 1];
        o1.z = s_e[kb * 8 + 2]; o1.w = s_e[kb * 8 + 3];
        o2.x = s_e[kb * 8 + 4]; o2.y = s_e[kb * 8 + 5];
        o2.z = s_e[kb * 8 + 6]; o2.w = s_e[kb * 8 + 7];
#pragma unroll
        for (int j = 0; j < 8; j++) {
            float d = s_e[kb * 8 + j] - v[u][j];
            sq += d * d;
        }
        ((float4*)q)[vi * 2]     = o1;
        ((float4*)q)[vi * 2 + 1] = o2;
    }

    s_red[tid] = (double)sq;
    __syncthreads();
    for (int o = 128; o > 0; o >>= 1) {
        if (tid < o) s_red[tid] += s_red[tid + o];
        __syncthreads();
    }
    if (tid == 0) part[blockIdx.x] = s_red[0];
}

__global__ void finalize_loss(const double* __restrict__ part, float* __restrict__ outp) {
    __shared__ double s[256];
    int tid = threadIdx.x;
    s[tid] = part[tid];
    __syncthreads();
    for (int o = 128; o > 0; o >>= 1) {
        if (tid < o) s[tid] += s[tid + o];
        __syncthreads();
    }
    if (tid == 0) *outp = (float)(1.25 * s[0] / 2097152.0);
}

// ---------------------------------------------------------------------------
extern "C" void kernel_launch(void* const* d_in, const int* in_sizes, int n_in,
                              void* d_out, int out_size) {
    (void)in_sizes; (void)n_in;
    const float* x   = (const float*)d_in[0];
    const float* e1w = (const float*)d_in[1];
    const float* e1b = (const float*)d_in[2];
    const float* e2w = (const float*)d_in[3];
    const float* e2b = (const float*)d_in[4];
    const float* e3w = (const float*)d_in[5];
    const float* e3b = (const float*)d_in[6];
    const float* emb = (const float*)d_in[7];
    const float* d1w = (const float*)d_in[8];
    const float* d1b = (const float*)d_in[9];
    const float* d2w = (const float*)d_in[10];
    const float* d2b = (const float*)d_in[11];
    const float* d3w = (const float*)d_in[12];
    const float* d3b = (const float*)d_in[13];
    float* out = (float*)d_out;

    void *z1, *z2, *z3, *q, *y1, *y2, *part;
    void *me1, *me2, *me3, *md1, *md2, *md3;
    cudaGetSymbolAddress(&z1,  g_z1);
    cudaGetSymbolAddress(&z2,  g_z2);
    cudaGetSymbolAddress(&z3,  g_z3);
    cudaGetSymbolAddress(&q,   g_q);
    cudaGetSymbolAddress(&y1,  g_y1);
    cudaGetSymbolAddress(&y2,  g_y2);
    cudaGetSymbolAddress(&me1, g_mw_e1);
    cudaGetSymbolAddress(&me2, g_mw_e2);
    cudaGetSymbolAddress(&me3, g_mw_e3);
    cudaGetSymbolAddress(&md1, g_mw_d1);
    cudaGetSymbolAddress(&md2, g_mw_d2);
    cudaGetSymbolAddress(&md3, g_mw_d3);
    cudaGetSymbolAddress(&part, g_part);

    // ---- one merged pack launch (529920 items)
    pack_all<<<(529920 + 255) / 256, 256>>>(
        e1w, e2w, e3w, d1w, d2w, d3w,
        (float*)me1, (float*)me2, (float*)me3,
        (float*)md1, (float*)md2, (float*)md3);

    // dynamic smem sizes (floats): 8*SLAB*136 + 9*MT*8
    const int SM_E1 = (8 * 3 * 136 + 9 * 128 * 8) * 4;  // 49920
    const int SM_E2 = (8 * 4 * 136 + 9 *  64 * 8) * 4;  // 35840
    const int SM_E3 = (8 * 6 * 136 + 9 *  16 * 8) * 4;  // 30720
    const int SM_D1 = SM_E2;
    const int SM_D2 = SM_E1;
    const int SM_D3 = (8 * 3 * 136 + 9 *  80 * 8) * 4;  // 36096

    cudaFuncSetAttribute((const void*)convmma<1, 156, 128, 128, 1, 0, 128, 2>,
                         cudaFuncAttributeMaxDynamicSharedMemorySize, SM_E1);
    cudaFuncSetAttribute((const void*)convmma<2, 128, 64, 64, 1, 0, 64, 2>,
                         cudaFuncAttributeMaxDynamicSharedMemorySize, SM_E2);
    cudaFuncSetAttribute((const void*)convmma<4, 64, 8, 16, 1, 0, 16, 3>,
                         cudaFuncAttributeMaxDynamicSharedMemorySize, SM_E3);
    cudaFuncSetAttribute((const void*)convmma<2, 8, 64, 64, 1, 0, 64, 2>,
                         cudaFuncAttributeMaxDynamicSharedMemorySize, SM_D1);
    cudaFuncSetAttribute((const void*)convmma<1, 64, 128, 128, 1, 0, 128, 2>,
                         cudaFuncAttributeMaxDynamicSharedMemorySize, SM_D2);
    cudaFuncSetAttribute((const void*)convmma<1, 128, 156, 80, 2, 0, 160, 2>,
                         cudaFuncAttributeMaxDynamicSharedMemorySize, SM_D3);

    // encoder (tf32 tensor path)
    convmma<1, 156, 128, 128, 1, 0, 128, 2><<<dim3(128, 1, 16), 256, SM_E1>>>(x, (float*)me1, e1b, (float*)z1);
    convmma<2, 128,  64,  64, 1, 0,  64, 2><<<dim3( 64, 1, 16), 256, SM_E2>>>((float*)z1, (float*)me2, e2b, (float*)z2);
    convmma<4,  64,   8,  16, 1, 0,  16, 3><<<dim3( 32, 1, 16), 256, SM_E3>>>((float*)z2, (float*)me3, e3b, (float*)z3);

    // vector quantizer + loss partials (exact fp32)
    vq_kernel<<<256, 256>>>((const float*)z3, emb, (float*)q, (double*)part);

    // decoder (tf32 tensor path)
    convmma<2,   8,  64,  64, 1, 0,  64, 2><<<dim3( 64, 1, 16), 256, SM_D1>>>((float*)q,  (float*)md1, d1b, (float*)y1);
    convmma<1,  64, 128, 128, 1, 0, 128, 2><<<dim3(128, 1, 16), 256, SM_D2>>>((float*)y1, (float*)md2, d2b, (float*)y2);
    convmma<1, 128, 156,  80, 2, 0, 160, 2><<<dim3(128, 2, 16), 256, SM_D3>>>((float*)y2, (float*)md3, d3b, out);

    finalize_loss<<<1, 256>>>((const double*)part, out + (out_size - 1));
}

// round 10
// speedup vs baseline: 1.1034x; 1.1034x over previous
#include <cuda_runtime.h>
#include <math.h>

// ---------------------------------------------------------------------------
// VQ-VAE forward.  B=16, L=156, P=8, H=W=128, codebook 512x8.
// R10: R8 structure + (a) B fragments via __ldg from packed gmem (no weight
//      smem stage), (b) double-buffered input smem with register prefetch,
//      one barrier per chunk.
// ---------------------------------------------------------------------------

#define BATCH 16
#define HW    16384   // 128*128

__device__ __forceinline__ float to_tf32(float x) {
    unsigned u; asm("cvt.rna.tf32.f32 %0, %1;" : "=r"(u) : "f"(x));
    return __uint_as_float(u);
}
__device__ __forceinline__ void mma_tf32(float c[4], const float a[4], float2 b) {
    asm volatile("mma.sync.aligned.m16n8k8.row.col.f32.tf32.tf32.f32 "
        "{%0,%1,%2,%3}, {%4,%5,%6,%7}, {%8,%9}, {%0,%1,%2,%3};"
        : "+f"(c[0]), "+f"(c[1]), "+f"(c[2]), "+f"(c[3])
        : "r"(__float_as_uint(a[0])), "r"(__float_as_uint(a[1])),
          "r"(__float_as_uint(a[2])), "r"(__float_as_uint(a[3])),
          "r"(__float_as_uint(b.x)), "r"(__float_as_uint(b.y)));
}

// Static device scratch (allocation-free rule).
__device__ float g_z1[BATCH * 128 * HW];
__device__ float g_z2[BATCH *  64 * HW];
__device__ float g_z3[BATCH *   8 * HW];
__device__ float g_q [BATCH *   8 * HW];
__device__ float g_y1[BATCH *  64 * HW];
__device__ float g_y2[BATCH * 128 * HW];
// tf32 mma weights: [chunk][tap 9][CO_PAD][8 ci-perm], perm p -> ci = (p>>1)+4*(p&1)
__device__ float g_mw_e1[20 * 9 * 128 * 8];
__device__ float g_mw_e2[16 * 9 *  64 * 8];
__device__ float g_mw_e3[ 8 * 9 *  16 * 8];
__device__ float g_mw_d1[ 1 * 9 *  64 * 8];
__device__ float g_mw_d2[ 8 * 9 * 128 * 8];
__device__ float g_mw_d3[16 * 9 * 160 * 8];
__device__ double g_part[256];

// ---------------------------------------------------------------------------
// Weight packing into mma layout.  transposed=0: Conv2d OIHW.
// transposed=1: ConvTranspose (in,out,kh,kw) -> IO swap + spatial flip.
// ---------------------------------------------------------------------------
__device__ void pack_mma(const float* __restrict__ w, float* __restrict__ out,
                         int CIN, int COUT, int CO_PAD, int transposed, int idx) {
    int p     = idx & 7;
    int co    = (idx >> 3) % CO_PAD;
    int tap   = ((idx >> 3) / CO_PAD) % 9;
    int chunk = ((idx >> 3) / CO_PAD) / 9;
    int ci    = chunk * 8 + (p >> 1) + 4 * (p & 1);
    float v = 0.f;
    if (co < COUT && ci < CIN)
        v = transposed ? w[((size_t)ci * COUT + co) * 9 + (8 - tap)]
                       : w[((size_t)co * CIN + ci) * 9 + tap];
    out[idx] = to_tf32(v);
}

__global__ void pack_all(const float* e1w, const float* e2w, const float* e3w,
                         const float* d1w, const float* d2w, const float* d3w,
                         float* me1, float* me2, float* me3,
                         float* md1, float* md2, float* md3) {
    int idx = blockIdx.x * 256 + threadIdx.x;
    if (idx < 184320) { pack_mma(e1w, me1, 156, 128, 128, 0, idx); return; }
    idx -= 184320;
    if (idx < 73728)  { pack_mma(e2w, me2, 128,  64,  64, 0, idx); return; }
    idx -= 73728;
    if (idx < 9216)   { pack_mma(e3w, me3,  64,   8,  16, 0, idx); return; }
    idx -= 9216;
    if (idx < 4608)   { pack_mma(d1w, md1,   8,  64,  64, 1, idx); return; }
    idx -= 4608;
    if (idx < 73728)  { pack_mma(d2w, md2,  64, 128, 128, 1, idx); return; }
    idx -= 73728;
    if (idx < 184320) { pack_mma(d3w, md3, 128, 156, 160, 1, idx); }
}

__device__ __forceinline__ float apply_act(float v, int ACT) {
    if (ACT == 1) return fmaxf(v, 0.f);
    if (ACT == 2) return 1.f / (1.f + __expf(-v));
    return v;
}

// ---------------------------------------------------------------------------
// tf32 tensor-core 3x3 same-conv (mma.sync m16n8k8).  R8 structure.
// Block = (n, row h, MT co at CO_OFF).  8 warps: wm=warp&3 -> 32-px span,
// wn=warp>>2 -> MT/2 co span.  B fragments read by __ldg directly from the
// packed weight tensor (L1-resident, coalesced 256B/warp).  Input slab
// double-buffered in smem with 3 float4/thread register prefetch; ONE
// __syncthreads per chunk (two-buffer hazard-free).
// ---------------------------------------------------------------------------
template<int CIN, int COUT, int MT, int ACT, int CO_OFF, int CO_PAD>
__global__ __launch_bounds__(256, 3)
void convmma(const float* __restrict__ in, const float* __restrict__ mw,
             const float* __restrict__ bias, float* __restrict__ out) {
    constexpr int CHUNKS = (CIN + 7) / 8;
    constexpr int ROWSTR = 136;
    constexpr int NT     = MT / 16;     // n-tiles per warp
    constexpr int INBUF  = 8 * 3 * ROWSTR;   // 3264 floats per buffer

    __shared__ float s_in[2 * INBUF];

    const int n    = blockIdx.z;
    const int h    = blockIdx.x;
    const int cob0 = CO_OFF + blockIdx.y * MT;
    const int tid  = threadIdx.x;
    const int lane = tid & 31;
    const int warp = tid >> 5;
    const int wm   = warp & 3;
    const int wn   = warp >> 2;
    const int r4   = lane & 3;    // t%4  (k index)
    const int r4h  = lane >> 2;   // t/4  (m/n index)
    const int pxb  = wm * 32;
    const int col  = wn * (MT / 2);

    const float* inN = in + (size_t)n * CIN * HW;

    // zero halo columns of both buffers once (48 rows total)
    if (tid < 48) {
        float* row = s_in + tid * ROWSTR;
        row[0] = 0.f; row[1] = 0.f; row[2] = 0.f; row[3] = 0.f;
        row[132] = 0.f; row[133] = 0.f; row[134] = 0.f; row[135] = 0.f;
    }

    // per-thread staging slots: s4 = tid + 256*j, j=0..2  (768 = 3*256)
    int  sm_off[3]; int g_off[3]; int kc_[3]; bool rowok[3];
#pragma unroll
    for (int j = 0; j < 3; j++) {
        int s4 = tid + 256 * j;
        int kc = s4 / 96;
        int r  = (s4 / 32) % 3;
        int s  = s4 & 31;
        int gh = h - 1 + r;
        kc_[j]    = kc;
        rowok[j]  = (gh >= 0 && gh < 128);
        sm_off[j] = (kc * 3 + r) * ROWSTR + 4 + s * 4;
        g_off[j]  = kc * HW + (rowok[j] ? gh : 0) * 128 + s * 4;
    }

    float C[2][NT][4];
#pragma unroll
    for (int mt = 0; mt < 2; mt++)
#pragma unroll
        for (int nt = 0; nt < NT; nt++)
#pragma unroll
            for (int k = 0; k < 4; k++) C[mt][nt][k] = 0.f;

    float4 pf[3];
    // prologue: prefetch chunk 0
#pragma unroll
    for (int j = 0; j < 3; j++) {
        int ci = kc_[j];
        float4 v = make_float4(0.f, 0.f, 0.f, 0.f);
        if (ci < CIN && rowok[j]) v = *(const float4*)(inN + g_off[j]);
        v.x = to_tf32(v.x); v.y = to_tf32(v.y);
        v.z = to_tf32(v.z); v.w = to_tf32(v.w);
        pf[j] = v;
    }

    for (int chunk = 0; chunk < CHUNKS; chunk++) {
        float* buf = s_in + (chunk & 1) * INBUF;
#pragma unroll
        for (int j = 0; j < 3; j++) *(float4*)(buf + sm_off[j]) = pf[j];
        __syncthreads();

        // prefetch next chunk (LDG latency hidden under compute)
        if (chunk + 1 < CHUNKS) {
#pragma unroll
            for (int j = 0; j < 3; j++) {
                int ci = (chunk + 1) * 8 + kc_[j];
                float4 v = make_float4(0.f, 0.f, 0.f, 0.f);
                if (ci < CIN && rowok[j])
                    v = *(const float4*)(inN + (size_t)(chunk + 1) * 8 * HW + g_off[j]);
                v.x = to_tf32(v.x); v.y = to_tf32(v.y);
                v.z = to_tf32(v.z); v.w = to_tf32(v.w);
                pf[j] = v;
            }
        }

        // B base for this chunk: co component fixed per thread
        const float* wc = mw + (((size_t)chunk * 9) * CO_PAD + cob0 + col + r4h) * 8 + r4 * 2;

#pragma unroll
        for (int dh = 0; dh < 3; dh++) {
#pragma unroll
            for (int dw = 0; dw < 3; dw++) {
                const int tap = dh * 3 + dw;
                float a[2][4];
                {
                    const float* base = buf + r4 * (3 * ROWSTR) + dh * ROWSTR
                                      + pxb + dw + 3 + r4h;
#pragma unroll
                    for (int mt = 0; mt < 2; mt++) {
                        a[mt][0] = base[mt * 16];
                        a[mt][1] = base[mt * 16 + 8];
                        a[mt][2] = base[4 * (3 * ROWSTR) + mt * 16];
                        a[mt][3] = base[4 * (3 * ROWSTR) + mt * 16 + 8];
                    }
                }
#pragma unroll
                for (int nt = 0; nt < NT; nt++) {
                    float2 b = __ldg((const float2*)(wc + ((size_t)tap * CO_PAD + nt * 8) * 8));
#pragma unroll
                    for (int mt = 0; mt < 2; mt++)
                        mma_tf32(C[mt][nt], a[mt], b);
                }
            }
        }
        // no trailing sync needed: next STS targets the other buffer
    }

    // ---- epilogue: c0 (px, co) c1 (px, co+1) c2 (px+8, co) c3 (px+8, co+1)
#pragma unroll
    for (int mt = 0; mt < 2; mt++) {
#pragma unroll
        for (int nt = 0; nt < NT; nt++) {
            int px = pxb + mt * 16 + r4h;
            int co = cob0 + col + nt * 8 + r4 * 2;
            size_t o0 = (size_t)h * 128 + px;
            if (co < COUT) {
                float b = bias[co];
                float* op = out + ((size_t)n * COUT + co) * HW;
                op[o0]     = apply_act(C[mt][nt][0] + b, ACT);
                op[o0 + 8] = apply_act(C[mt][nt][2] + b, ACT);
            }
            if (co + 1 < COUT) {
                float b = bias[co + 1];
                float* op = out + ((size_t)n * COUT + co + 1) * HW;
                op[o0]     = apply_act(C[mt][nt][1] + b, ACT);
                op[o0 + 8] = apply_act(C[mt][nt][3] + b, ACT);
            }
        }
    }
}

// ---------------------------------------------------------------------------
// Vector quantizer (groups of 8 along W, torch .view semantics).
// ---------------------------------------------------------------------------
__global__ __launch_bounds__(256)
void vq_kernel(const float* __restrict__ z, const float* __restrict__ emb,
               float* __restrict__ q, double* __restrict__ part) {
    __shared__ float  s_e[512 * 8];
    __shared__ float  s_hn[512];
    __shared__ double s_red[256];

    const int tid = threadIdx.x;
    for (int i = tid; i < 4096; i += 256) s_e[i] = emb[i];
    __syncthreads();
    for (int k = tid; k < 512; k += 256) {
        float s = 0.f;
#pragma unroll
        for (int j = 0; j < 8; j++) { float e = s_e[k * 8 + j]; s += e * e; }
        s_hn[k] = 0.5f * s;
    }
    __syncthreads();

    const int base = blockIdx.x * 1024 + tid;
    float v[4][8];
#pragma unroll
    for (int u = 0; u < 4; u++) {
        int vi = base + u * 256;
        float4 a = ((const float4*)z)[vi * 2];
        float4 b = ((const float4*)z)[vi * 2 + 1];
        v[u][0] = a.x; v[u][1] = a.y; v[u][2] = a.z; v[u][3] = a.w;
        v[u][4] = b.x; v[u][5] = b.y; v[u][6] = b.z; v[u][7] = b.w;
    }

    float best[4] = {3.4e38f, 3.4e38f, 3.4e38f, 3.4e38f};
    int   bk[4]   = {0, 0, 0, 0};
    for (int k = 0; k < 512; k++) {
        float e0 = s_e[k * 8 + 0], e1 = s_e[k * 8 + 1], e2 = s_e[k * 8 + 2], e3 = s_e[k * 8 + 3];
        float e4 = s_e[k * 8 + 4], e5 = s_e[k * 8 + 5], e6 = s_e[k * 8 + 6], e7 = s_e[k * 8 + 7];
        float hn = s_hn[k];
#pragma unroll
        for (int u = 0; u < 4; u++) {
            float dot = e0 * v[u][0] + e1 * v[u][1] + e2 * v[u][2] + e3 * v[u][3]
                      + e4 * v[u][4] + e5 * v[u][5] + e6 * v[u][6] + e7 * v[u][7];
            float sc = hn - dot;
            if (sc < best[u]) { best[u] = sc; bk[u] = k; }
        }
    }

    float sq = 0.f;
#pragma unroll
    for (int u = 0; u < 4; u++) {
        int vi = base + u * 256;
        int kb = bk[u];
        float4 o1, o2;
        o1.x = s_e[kb * 8 + 0]; o1.y = s_e[kb * 8 + 1];
        o1.z = s_e[kb * 8 + 2]; o1.w = s_e[kb * 8 + 3];
        o2.x = s_e[kb * 8 + 4]; o2.y = s_e[kb * 8 + 5];
        o2.z = s_e[kb * 8 + 6]; o2.w = s_e[kb * 8 + 7];
#pragma unroll
        for (int j = 0; j < 8; j++) {
            float d = s_e[kb * 8 + j] - v[u][j];
            sq += d * d;
        }
        ((float4*)q)[vi * 2]     = o1;
        ((float4*)q)[vi * 2 + 1] = o2;
    }

    s_red[tid] = (double)sq;
    __syncthreads();
    for (int o = 128; o > 0; o >>= 1) {
        if (tid < o) s_red[tid] += s_red[tid + o];
        __syncthreads();
    }
    if (tid == 0) part[blockIdx.x] = s_red[0];
}

__global__ void finalize_loss(const double* __restrict__ part, float* __restrict__ outp) {
    __shared__ double s[256];
    int tid = threadIdx.x;
    s[tid] = part[tid];
    __syncthreads();
    for (int o = 128; o > 0; o >>= 1) {
        if (tid < o) s[tid] += s[tid + o];
        __syncthreads();
    }
    if (tid == 0) *outp = (float)(1.25 * s[0] / 2097152.0);
}

// ---------------------------------------------------------------------------
extern "C" void kernel_launch(void* const* d_in, const int* in_sizes, int n_in,
                              void* d_out, int out_size) {
    (void)in_sizes; (void)n_in;
    const float* x   = (const float*)d_in[0];
    const float* e1w = (const float*)d_in[1];
    const float* e1b = (const float*)d_in[2];
    const float* e2w = (const float*)d_in[3];
    const float* e2b = (const float*)d_in[4];
    const float* e3w = (const float*)d_in[5];
    const float* e3b = (const float*)d_in[6];
    const float* emb = (const float*)d_in[7];
    const float* d1w = (const float*)d_in[8];
    const float* d1b = (const float*)d_in[9];
    const float* d2w = (const float*)d_in[10];
    const float* d2b = (const float*)d_in[11];
    const float* d3w = (const float*)d_in[12];
    const float* d3b = (const float*)d_in[13];
    float* out = (float*)d_out;

    void *z1, *z2, *z3, *q, *y1, *y2, *part;
    void *me1, *me2, *me3, *md1, *md2, *md3;
    cudaGetSymbolAddress(&z1,  g_z1);
    cudaGetSymbolAddress(&z2,  g_z2);
    cudaGetSymbolAddress(&z3,  g_z3);
    cudaGetSymbolAddress(&q,   g_q);
    cudaGetSymbolAddress(&y1,  g_y1);
    cudaGetSymbolAddress(&y2,  g_y2);
    cudaGetSymbolAddress(&me1, g_mw_e1);
    cudaGetSymbolAddress(&me2, g_mw_e2);
    cudaGetSymbolAddress(&me3, g_mw_e3);
    cudaGetSymbolAddress(&md1, g_mw_d1);
    cudaGetSymbolAddress(&md2, g_mw_d2);
    cudaGetSymbolAddress(&md3, g_mw_d3);
    cudaGetSymbolAddress(&part, g_part);

    // ---- one merged pack launch (529920 items)
    pack_all<<<(529920 + 255) / 256, 256>>>(
        e1w, e2w, e3w, d1w, d2w, d3w,
        (float*)me1, (float*)me2, (float*)me3,
        (float*)md1, (float*)md2, (float*)md3);

    // encoder (tf32 tensor path)
    convmma<156, 128, 64, 1, 0, 128><<<dim3(128, 2, 16), 256>>>(x, (float*)me1, e1b, (float*)z1);
    convmma<128,  64, 64, 1, 0,  64><<<dim3(128, 1, 16), 256>>>((float*)z1, (float*)me2, e2b, (float*)z2);
    convmma< 64,   8, 16, 1, 0,  16><<<dim3(128, 1, 16), 256>>>((float*)z2, (float*)me3, e3b, (float*)z3);

    // vector quantizer + loss partials (exact fp32)
    vq_kernel<<<256, 256>>>((const float*)z3, emb, (float*)q, (double*)part);

    // decoder (tf32 tensor path)
    convmma<  8,  64, 64, 1, 0,   64><<<dim3(128, 1, 16), 256>>>((float*)q,  (float*)md1, d1b, (float*)y1);
    convmma< 64, 128, 64, 1, 0,  128><<<dim3(128, 2, 16), 256>>>((float*)y1, (float*)md2, d2b, (float*)y2);
    convmma<128, 156, 64, 2, 0,  160><<<dim3(128, 2, 16), 256>>>((float*)y2, (float*)md3, d3b, out);
    convmma<128, 156, 32, 2, 128,160><<<dim3(128, 1, 16), 256>>>((float*)y2, (float*)md3, d3b, out);

    finalize_loss<<<1, 256>>>((const double*)part, out + (out_size - 1));
}